// round 13
// baseline (speedup 1.0000x reference)
#include <cuda_runtime.h>
#include <cuda_bf16.h>

#define S_LEN  1024
#define D_DIM  1024
#define N_ST   64
#define B_SZ   16
#define M_TOT  (B_SZ * S_LEN)

typedef unsigned long long u64;

// ---------------------------------------------------------------------------
// Scratch (device globals; no runtime allocation allowed)
// ---------------------------------------------------------------------------
__device__ float g_sgA[D_DIM * N_ST];
__device__ float g_sgB[N_ST * D_DIM];
__device__ float g_sgC[D_DIM * N_ST];
__device__ float g_sgG[D_DIM];
__device__ float g_sumC[D_DIM];                    // full 64-sum of sgC per d
__device__ float g_bproj[M_TOT * N_ST];
__device__ float g_minb[M_TOT];                    // min_n bproj[row, n]
__device__ float g_yraw[(size_t)M_TOT * D_DIM];    // sparse corrections only

__device__ __forceinline__ float sigf(float v) { return 1.0f / (1.0f + expf(-v)); }

// ---- packed f32x2 helpers (Blackwell sm_103a) ------------------------------
__device__ __forceinline__ u64 pk2(float lo, float hi) {
    u64 r; asm("mov.b64 %0, {%1, %2};" : "=l"(r) : "f"(lo), "f"(hi)); return r;
}
__device__ __forceinline__ void upk2(u64 v, float& lo, float& hi) {
    asm("mov.b64 {%0, %1}, %2;" : "=f"(lo), "=f"(hi) : "l"(v));
}
__device__ __forceinline__ u64 fma2_(u64 a, u64 b, u64 c) {
    u64 d; asm("fma.rn.f32x2 %0, %1, %2, %3;" : "=l"(d) : "l"(a), "l"(b), "l"(c)); return d;
}
__device__ __forceinline__ u64 add2_(u64 a, u64 b) {
    u64 d; asm("add.rn.f32x2 %0, %1, %2;" : "=l"(d) : "l"(a), "l"(b)); return d;
}

// ---------------------------------------------------------------------------
// K1: precompute sigmoids + sumC
// ---------------------------------------------------------------------------
__global__ void precompute_kernel(const float* __restrict__ A,
                                  const float* __restrict__ WB,
                                  const float* __restrict__ WC,
                                  const float* __restrict__ gamma) {
    int i = blockIdx.x * blockDim.x + threadIdx.x;
    if (i < D_DIM * N_ST) {
        g_sgA[i] = sigf(A[i]);
        g_sgB[i] = sigf(WB[i]);
        g_sgC[i] = sigf(WC[i]);
    }
    if (i < D_DIM) {
        g_sgG[i] = sigf(gamma[i]);
        const float* c = WC + (size_t)i * N_ST;
        float s = 0.0f;
        #pragma unroll
        for (int q = 0; q < N_ST; q++) s += sigf(c[q]);
        g_sumC[i] = s;
    }
}

// ---------------------------------------------------------------------------
// K2: Bproj = x @ sgB.T (M=16384, K=1024, N=64), split-K within the CTA.
// 512 threads: warpgroup 0 -> k[0,512), warpgroup 1 -> k[512,1024), each
// with R10's proven per-thread shape (4m x 8n, 16 fma2 per 48B LDS) and its
// own smem double-buffer + named barrier. Cross-group smem reduction at the
// end (packed f32x2 adds), fused row-min. Grid 128 -> 16 warps/SM.
// ---------------------------------------------------------------------------
__global__ __launch_bounds__(512) void bproj_gemm(const float* __restrict__ X) {
    __shared__ __align__(16) float sm[12288];       // 48 KB exactly
    const int tid = threadIdx.x;
    const int g   = tid >> 8;                       // K-group (0 or 1)
    const int wt  = tid & 255;

    float* xs = sm + g * 6144;                      // [2][16][128] floats
    float* bs = xs + 4096;                          // [2][16][64]  floats

    const int m0   = blockIdx.x * 128;
    const int trow = wt >> 3;                       // 0..31 -> rows trow*4..+3
    const int tcol = wt & 7;                        // 0..7  -> cols tcol*8..+7
    const int kb   = g * 512;

    u64 acc[4][4];
    #pragma unroll
    for (int i = 0; i < 4; i++)
        #pragma unroll
        for (int j = 0; j < 4; j++) acc[i][j] = 0ull;

    const int xm = wt & 127, xkq = wt >> 7;         // x: 2 float4/thread
    const int bn = wt & 63,  bkq = wt >> 6;         // b: 1 float4/thread

    // prologue: stage 0 of this group's K half
    {
        const float4* xg = (const float4*)(X + (size_t)(m0 + xm) * D_DIM + kb + xkq * 8);
        #pragma unroll
        for (int j = 0; j < 2; j++) {
            float4 v = xg[j];
            const int k = xkq * 8 + j * 4;
            xs[(k + 0) * 128 + xm] = v.x; xs[(k + 1) * 128 + xm] = v.y;
            xs[(k + 2) * 128 + xm] = v.z; xs[(k + 3) * 128 + xm] = v.w;
        }
        float4 w = *(const float4*)(g_sgB + (size_t)bn * D_DIM + kb + bkq * 4);
        const int k = bkq * 4;
        bs[(k + 0) * 64 + bn] = w.x; bs[(k + 1) * 64 + bn] = w.y;
        bs[(k + 2) * 64 + bn] = w.z; bs[(k + 3) * 64 + bn] = w.w;
    }
    asm volatile("bar.sync %0, 256;" :: "r"(1 + g) : "memory");

    for (int it = 0; it < 32; it++) {
        const int cur = it & 1, nxt = cur ^ 1;
        float4 xr0, xr1, br;
        if (it < 31) {
            const int k0 = kb + (it + 1) * 16;
            const float4* xg = (const float4*)(X + (size_t)(m0 + xm) * D_DIM + k0 + xkq * 8);
            xr0 = xg[0];
            xr1 = xg[1];
            br  = *(const float4*)(g_sgB + (size_t)bn * D_DIM + k0 + bkq * 4);
        }

        #pragma unroll
        for (int kk = 0; kk < 16; kk++) {
            float4 xv = *(const float4*)&xs[(cur * 16 + kk) * 128 + trow * 4];
            const ulonglong2* brow = (const ulonglong2*)&bs[(cur * 16 + kk) * 64];
            ulonglong2 b01 = brow[tcol * 2 + 0];
            ulonglong2 b23 = brow[tcol * 2 + 1];
            u64 xd[4];
            xd[0] = pk2(xv.x, xv.x); xd[1] = pk2(xv.y, xv.y);
            xd[2] = pk2(xv.z, xv.z); xd[3] = pk2(xv.w, xv.w);
            #pragma unroll
            for (int i = 0; i < 4; i++) {
                acc[i][0] = fma2_(b01.x, xd[i], acc[i][0]);
                acc[i][1] = fma2_(b01.y, xd[i], acc[i][1]);
                acc[i][2] = fma2_(b23.x, xd[i], acc[i][2]);
                acc[i][3] = fma2_(b23.y, xd[i], acc[i][3]);
            }
        }

        if (it < 31) {
            const int k = xkq * 8;
            xs[(nxt * 16 + k + 0) * 128 + xm] = xr0.x;
            xs[(nxt * 16 + k + 1) * 128 + xm] = xr0.y;
            xs[(nxt * 16 + k + 2) * 128 + xm] = xr0.z;
            xs[(nxt * 16 + k + 3) * 128 + xm] = xr0.w;
            xs[(nxt * 16 + k + 4) * 128 + xm] = xr1.x;
            xs[(nxt * 16 + k + 5) * 128 + xm] = xr1.y;
            xs[(nxt * 16 + k + 6) * 128 + xm] = xr1.z;
            xs[(nxt * 16 + k + 7) * 128 + xm] = xr1.w;
            const int kbs = bkq * 4;
            bs[(nxt * 16 + kbs + 0) * 64 + bn] = br.x;
            bs[(nxt * 16 + kbs + 1) * 64 + bn] = br.y;
            bs[(nxt * 16 + kbs + 2) * 64 + bn] = br.z;
            bs[(nxt * 16 + kbs + 3) * 64 + bn] = br.w;
        }
        asm volatile("bar.sync %0, 256;" :: "r"(1 + g) : "memory");
    }

    // ---- cross-group reduction (smem reused; both groups done with tiles) --
    __syncthreads();
    float* red = sm;                                // 128 rows x 64 cols
    if (g == 1) {
        #pragma unroll
        for (int i = 0; i < 4; i++) {
            ulonglong2* p = (ulonglong2*)&red[(trow * 4 + i) * 64 + tcol * 8];
            p[0] = make_ulonglong2(acc[i][0], acc[i][1]);
            p[1] = make_ulonglong2(acc[i][2], acc[i][3]);
        }
    }
    __syncthreads();
    if (g == 0) {
        #pragma unroll
        for (int i = 0; i < 4; i++) {
            const int lrow = trow * 4 + i;
            const ulonglong2* q = (const ulonglong2*)&red[lrow * 64 + tcol * 8];
            ulonglong2 q0 = q[0], q1 = q[1];
            acc[i][0] = add2_(acc[i][0], q0.x);
            acc[i][1] = add2_(acc[i][1], q0.y);
            acc[i][2] = add2_(acc[i][2], q1.x);
            acc[i][3] = add2_(acc[i][3], q1.y);

            const int row = m0 + lrow;
            ulonglong2* p = (ulonglong2*)(g_bproj + (size_t)row * N_ST + tcol * 8);
            p[0] = make_ulonglong2(acc[i][0], acc[i][1]);
            p[1] = make_ulonglong2(acc[i][2], acc[i][3]);

            float mn = 1e30f;
            #pragma unroll
            for (int j = 0; j < 4; j++) {
                float lo, hi;
                upk2(acc[i][j], lo, hi);
                mn = fminf(mn, fminf(lo, hi));
            }
            mn = fminf(mn, __shfl_xor_sync(0xffffffffu, mn, 1));
            mn = fminf(mn, __shfl_xor_sync(0xffffffffu, mn, 2));
            mn = fminf(mn, __shfl_xor_sync(0xffffffffu, mn, 4));
            if (tcol == 0) g_minb[row] = mn;
        }
    }
}

__global__ void noop_kernel() {}

// ---------------------------------------------------------------------------
// K3: fused scan+fix. Each thread owns 32 consecutive elements of one (b,t)
// row: computes the non-sat bits, then immediately repairs each one by
// walking back to the last saturating step (h there = exactly 1 for all n)
// and recurring forward. ~0.4% of elements take the repair path.
// ---------------------------------------------------------------------------
__device__ void fix_one(const float* __restrict__ x, int row0, int t, int d) {
    int s = t - 1;
    while (s >= 0) {
        float xs = x[((size_t)(row0 + s) << 10) + d];
        if (xs * g_minb[row0 + s] >= 1.0f) break;
        s--;
    }
    float h[N_ST];
    const float hinit = (s >= 0) ? 1.0f : 0.0f;
    #pragma unroll
    for (int n = 0; n < N_ST; n++) h[n] = hinit;

    const float4* ar = (const float4*)(g_sgA + (size_t)d * N_ST);
    for (int u = s + 1; u <= t; u++) {
        const float xu = x[((size_t)(row0 + u) << 10) + d];
        const float4* bp = (const float4*)(g_bproj + ((size_t)(row0 + u) << 6));
        #pragma unroll
        for (int q = 0; q < 16; q++) {
            float4 av = ar[q];
            float4 bv = bp[q];
            h[4 * q + 0] = fminf(fmaf(bv.x, xu, h[4 * q + 0] * av.x), 1.0f);
            h[4 * q + 1] = fminf(fmaf(bv.y, xu, h[4 * q + 1] * av.y), 1.0f);
            h[4 * q + 2] = fminf(fmaf(bv.z, xu, h[4 * q + 2] * av.z), 1.0f);
            h[4 * q + 3] = fminf(fmaf(bv.w, xu, h[4 * q + 3] * av.w), 1.0f);
        }
    }

    const float4* cr = (const float4*)(g_sgC + (size_t)d * N_ST);
    float y0 = 0.f, y1 = 0.f, y2 = 0.f, y3 = 0.f;
    #pragma unroll
    for (int q = 0; q < 16; q++) {
        float4 cv = cr[q];
        y0 = fmaf(h[4 * q + 0], cv.x, y0);
        y1 = fmaf(h[4 * q + 1], cv.y, y1);
        y2 = fmaf(h[4 * q + 2], cv.z, y2);
        y3 = fmaf(h[4 * q + 3], cv.w, y3);
    }
    g_yraw[((size_t)(row0 + t) << 10) + d] = (y0 + y1) + (y2 + y3);
}

__global__ __launch_bounds__(256) void scanfix_kernel(const float* __restrict__ x) {
    const int w   = blockIdx.x * 256 + threadIdx.x;      // word index
    const int row = w >> 5;                               // (b*S + t)
    const float mb = g_minb[row];
    const float4* xp = (const float4*)(x + ((size_t)w << 5));

    unsigned m = 0u;
    #pragma unroll
    for (int j = 0; j < 8; j++) {
        float4 v = xp[j];
        if (v.x * mb < 1.0f) m |= 1u << (4 * j + 0);
        if (v.y * mb < 1.0f) m |= 1u << (4 * j + 1);
        if (v.z * mb < 1.0f) m |= 1u << (4 * j + 2);
        if (v.w * mb < 1.0f) m |= 1u << (4 * j + 3);
    }
    if (m == 0u) return;

    const int row0  = row & ~(S_LEN - 1);
    const int t     = row & (S_LEN - 1);
    const int dbase = (w & 31) * 32;
    while (m) {
        const int c = __ffs(m) - 1;
        m &= m - 1;
        fix_one(x, row0, t, dbase + c);
    }
}

// ---------------------------------------------------------------------------
// K4: TopologicalNorm + residual + clip. y per element: sat (x*minb>=1, same
// fp test as scanfix) -> sumC[d]; else the fixer's scattered correction.
// ---------------------------------------------------------------------------
__global__ __launch_bounds__(256) void ln_kernel(const float* __restrict__ x,
                                                 float* __restrict__ out) {
    const int row  = blockIdx.x * 8 + (threadIdx.x >> 5);
    const int lane = threadIdx.x & 31;

    const float mb = g_minb[row];
    const float* yrawr = g_yraw + ((size_t)row << 10);
    const float4* xr   = (const float4*)(x + ((size_t)row << 10));
    float4*       orow = (float4*)(out + ((size_t)row << 10));
    const float4* gr   = (const float4*)g_sgG;
    const float4* sr   = (const float4*)g_sumC;

    float4 v[8], xv[8];
    float sum = 0.0f;
    #pragma unroll
    for (int i = 0; i < 8; i++) {
        const int idx = lane + 32 * i;
        float4 x4 = xr[idx];
        float4 s4 = sr[idx];
        float4 y4;
        y4.x = (x4.x * mb >= 1.0f) ? s4.x : yrawr[4 * idx + 0];
        y4.y = (x4.y * mb >= 1.0f) ? s4.y : yrawr[4 * idx + 1];
        y4.z = (x4.z * mb >= 1.0f) ? s4.z : yrawr[4 * idx + 2];
        y4.w = (x4.w * mb >= 1.0f) ? s4.w : yrawr[4 * idx + 3];
        v[i] = y4;
        xv[i] = x4;
        sum += (y4.x + y4.y) + (y4.z + y4.w);
    }
    #pragma unroll
    for (int o = 16; o > 0; o >>= 1) sum += __shfl_xor_sync(0xffffffffu, sum, o);
    const float mean = sum * (1.0f / 1024.0f);

    float ss = 0.0f;
    #pragma unroll
    for (int i = 0; i < 8; i++) {
        float dx = v[i].x - mean, dy = v[i].y - mean;
        float dz = v[i].z - mean, dw = v[i].w - mean;
        ss += (dx * dx + dy * dy) + (dz * dz + dw * dw);
    }
    #pragma unroll
    for (int o = 16; o > 0; o >>= 1) ss += __shfl_xor_sync(0xffffffffu, ss, o);
    const float rstd = rsqrtf(ss * (1.0f / 1024.0f) + 1e-5f);

    #pragma unroll
    for (int i = 0; i < 8; i++) {
        float4 g4 = gr[lane + 32 * i];
        float4 o4;
        o4.x = fminf(fmaxf((v[i].x - mean) * rstd * g4.x + xv[i].x, 0.0f), 1.0f);
        o4.y = fminf(fmaxf((v[i].y - mean) * rstd * g4.y + xv[i].y, 0.0f), 1.0f);
        o4.z = fminf(fmaxf((v[i].z - mean) * rstd * g4.z + xv[i].z, 0.0f), 1.0f);
        o4.w = fminf(fmaxf((v[i].w - mean) * rstd * g4.w + xv[i].w, 0.0f), 1.0f);
        orow[lane + 32 * i] = o4;
    }
}

// ---------------------------------------------------------------------------
// ncu captures 0-based launch index 3 -> split-K bproj_gemm this round.
// ---------------------------------------------------------------------------
extern "C" void kernel_launch(void* const* d_in, const int* in_sizes, int n_in,
                              void* d_out, int out_size) {
    const float* x     = (const float*)d_in[0];
    const float* A     = (const float*)d_in[1];
    const float* WB    = (const float*)d_in[2];
    const float* WC    = (const float*)d_in[3];
    const float* gamma = (const float*)d_in[4];
    float* out = (float*)d_out;

    noop_kernel<<<1, 32>>>();                              // 0
    noop_kernel<<<1, 32>>>();                              // 1
    precompute_kernel<<<256, 256>>>(A, WB, WC, gamma);     // 2
    bproj_gemm<<<M_TOT / 128, 512>>>(x);                   // 3  <- profiled
    scanfix_kernel<<<M_TOT * D_DIM / 32 / 256, 256>>>(x);  // 4
    ln_kernel<<<M_TOT / 8, 256>>>(x, out);                 // 5
}

// round 16
// speedup vs baseline: 1.6565x; 1.6565x over previous
#include <cuda_runtime.h>
#include <cuda_bf16.h>
#include <cstdint>

#define S_LEN  1024
#define D_DIM  1024
#define N_ST   64
#define B_SZ   16
#define M_TOT  (B_SZ * S_LEN)
#define KSPLIT 4

typedef unsigned long long u64;

// ---------------------------------------------------------------------------
// Scratch (device globals; no runtime allocation allowed)
// ---------------------------------------------------------------------------
__device__ float g_sgA[D_DIM * N_ST];
__device__ float g_sgB[N_ST * D_DIM];
__device__ float g_sgC[D_DIM * N_ST];
__device__ float g_sgG[D_DIM];
__device__ float g_sumC[D_DIM];
__device__ float g_part[(size_t)KSPLIT * M_TOT * N_ST];   // split-K partials (16 MB)
__device__ float g_bproj[M_TOT * N_ST];
__device__ float g_minb[M_TOT];
__device__ float g_yraw[(size_t)M_TOT * D_DIM];

__device__ __forceinline__ float sigf(float v) { return 1.0f / (1.0f + expf(-v)); }

// ---- packed f32x2 helpers (Blackwell sm_103a; PTX-portable, no tcgen05) ----
__device__ __forceinline__ u64 pk2(float lo, float hi) {
    u64 r; asm("mov.b64 %0, {%1, %2};" : "=l"(r) : "f"(lo), "f"(hi)); return r;
}
__device__ __forceinline__ void upk2(u64 v, float& lo, float& hi) {
    asm("mov.b64 {%0, %1}, %2;" : "=f"(lo), "=f"(hi) : "l"(v));
}
__device__ __forceinline__ u64 fma2_(u64 a, u64 b, u64 c) {
    u64 d; asm("fma.rn.f32x2 %0, %1, %2, %3;" : "=l"(d) : "l"(a), "l"(b), "l"(c)); return d;
}

// ---------------------------------------------------------------------------
// K1: precompute sigmoids + sumC
// ---------------------------------------------------------------------------
__global__ void precompute_kernel(const float* __restrict__ A,
                                  const float* __restrict__ WB,
                                  const float* __restrict__ WC,
                                  const float* __restrict__ gamma) {
    int i = blockIdx.x * blockDim.x + threadIdx.x;
    if (i < D_DIM * N_ST) {
        g_sgA[i] = sigf(A[i]);
        g_sgB[i] = sigf(WB[i]);
        g_sgC[i] = sigf(WC[i]);
    }
    if (i < D_DIM) {
        g_sgG[i] = sigf(gamma[i]);
        const float* c = WC + (size_t)i * N_ST;
        float s = 0.0f;
        #pragma unroll
        for (int q = 0; q < N_ST; q++) s += sigf(c[q]);
        g_sumC[i] = s;
    }
}

// ---------------------------------------------------------------------------
// K2: split-K GEMM partials. grid = 128 m-tiles x 4 k-splits = 512 CTAs
// (~3.5 independent CTAs/SM). 128 threads, thread tile 8m x 8n (32 fma2/kk),
// double-buffered smem, K=256 per CTA in 16 BK=16 iterations.
// ---------------------------------------------------------------------------
__global__ __launch_bounds__(128, 4) void bproj_gemm(const float* __restrict__ X) {
    __shared__ __align__(16) float xs[2][16][128];   // 16 KB
    __shared__ __align__(16) float bs[2][16][64];    // 8 KB

    const int mt = blockIdx.x >> 2;
    const int ks = blockIdx.x & 3;
    const int m0 = mt * 128;
    const int kb = ks * 256;

    const int tid  = threadIdx.x;
    const int trow = tid >> 3;      // 0..15 -> rows trow*8 .. +7
    const int tcol = tid & 7;       // 0..7  -> cols tcol*8 .. +7 (4 n-pairs)

    u64 acc[8][4];                  // [m][n-pair]
    #pragma unroll
    for (int i = 0; i < 8; i++)
        #pragma unroll
        for (int j = 0; j < 4; j++) acc[i][j] = 0ull;

    const int bn = tid & 63, bkq = tid >> 6;   // b: 2 float4/thread (8 k)

    // prologue: stage 0
    {
        const float4* xg = (const float4*)(X + (size_t)(m0 + tid) * D_DIM + kb);
        #pragma unroll
        for (int j = 0; j < 4; j++) {
            float4 v = xg[j];
            xs[0][j * 4 + 0][tid] = v.x; xs[0][j * 4 + 1][tid] = v.y;
            xs[0][j * 4 + 2][tid] = v.z; xs[0][j * 4 + 3][tid] = v.w;
        }
        const float4* bg = (const float4*)(g_sgB + (size_t)bn * D_DIM + kb + bkq * 8);
        #pragma unroll
        for (int j = 0; j < 2; j++) {
            float4 v = bg[j];
            const int k = bkq * 8 + j * 4;
            bs[0][k + 0][bn] = v.x; bs[0][k + 1][bn] = v.y;
            bs[0][k + 2][bn] = v.z; bs[0][k + 3][bn] = v.w;
        }
    }
    __syncthreads();

    for (int it = 0; it < 16; it++) {
        const int cur = it & 1, nxt = cur ^ 1;
        float4 xr[4], br[2];
        if (it < 15) {
            const int k0 = kb + (it + 1) * 16;
            const float4* xg = (const float4*)(X + (size_t)(m0 + tid) * D_DIM + k0);
            #pragma unroll
            for (int j = 0; j < 4; j++) xr[j] = xg[j];
            const float4* bg = (const float4*)(g_sgB + (size_t)bn * D_DIM + k0 + bkq * 8);
            br[0] = bg[0];
            br[1] = bg[1];
        }

        #pragma unroll
        for (int kk = 0; kk < 16; kk++) {
            float4 xv0 = *(const float4*)&xs[cur][kk][trow * 8];
            float4 xv1 = *(const float4*)&xs[cur][kk][trow * 8 + 4];
            const ulonglong2* brow = (const ulonglong2*)&bs[cur][kk][0];
            ulonglong2 b01 = brow[tcol * 2 + 0];
            ulonglong2 b23 = brow[tcol * 2 + 1];
            u64 xd[8];
            xd[0] = pk2(xv0.x, xv0.x); xd[1] = pk2(xv0.y, xv0.y);
            xd[2] = pk2(xv0.z, xv0.z); xd[3] = pk2(xv0.w, xv0.w);
            xd[4] = pk2(xv1.x, xv1.x); xd[5] = pk2(xv1.y, xv1.y);
            xd[6] = pk2(xv1.z, xv1.z); xd[7] = pk2(xv1.w, xv1.w);
            #pragma unroll
            for (int i = 0; i < 8; i++) {
                acc[i][0] = fma2_(b01.x, xd[i], acc[i][0]);
                acc[i][1] = fma2_(b01.y, xd[i], acc[i][1]);
                acc[i][2] = fma2_(b23.x, xd[i], acc[i][2]);
                acc[i][3] = fma2_(b23.y, xd[i], acc[i][3]);
            }
        }

        if (it < 15) {
            #pragma unroll
            for (int j = 0; j < 4; j++) {
                xs[nxt][j * 4 + 0][tid] = xr[j].x;
                xs[nxt][j * 4 + 1][tid] = xr[j].y;
                xs[nxt][j * 4 + 2][tid] = xr[j].z;
                xs[nxt][j * 4 + 3][tid] = xr[j].w;
            }
            #pragma unroll
            for (int j = 0; j < 2; j++) {
                const int k = bkq * 8 + j * 4;
                bs[nxt][k + 0][bn] = br[j].x;
                bs[nxt][k + 1][bn] = br[j].y;
                bs[nxt][k + 2][bn] = br[j].z;
                bs[nxt][k + 3][bn] = br[j].w;
            }
        }
        __syncthreads();
    }

    // writeback partials (no unpack: acc pairs are along n, rows independent)
    float* base = g_part + ((size_t)ks * M_TOT + m0) * N_ST;
    #pragma unroll
    for (int i = 0; i < 8; i++) {
        ulonglong2* p = (ulonglong2*)(base + (size_t)(trow * 8 + i) * N_ST + tcol * 8);
        p[0] = make_ulonglong2(acc[i][0], acc[i][1]);
        p[1] = make_ulonglong2(acc[i][2], acc[i][3]);
    }
}

// ---------------------------------------------------------------------------
// K2b: reduce the 4 partials -> g_bproj + exact row-min g_minb.
// One thread per row (16384 threads); partials are L2-resident (16 MB).
// ---------------------------------------------------------------------------
__global__ __launch_bounds__(256) void reduce_kernel() {
    const int row = blockIdx.x * 256 + threadIdx.x;
    const float4* p0 = (const float4*)(g_part + ((size_t)0 * M_TOT + row) * N_ST);
    const float4* p1 = (const float4*)(g_part + ((size_t)1 * M_TOT + row) * N_ST);
    const float4* p2 = (const float4*)(g_part + ((size_t)2 * M_TOT + row) * N_ST);
    const float4* p3 = (const float4*)(g_part + ((size_t)3 * M_TOT + row) * N_ST);
    float4* dst = (float4*)(g_bproj + (size_t)row * N_ST);

    float mn = 1e30f;
    #pragma unroll
    for (int q = 0; q < 16; q++) {
        float4 a = p0[q], b = p1[q], c = p2[q], d = p3[q];
        float4 s;
        s.x = (a.x + b.x) + (c.x + d.x);
        s.y = (a.y + b.y) + (c.y + d.y);
        s.z = (a.z + b.z) + (c.z + d.z);
        s.w = (a.w + b.w) + (c.w + d.w);
        mn = fminf(mn, fminf(fminf(s.x, s.y), fminf(s.z, s.w)));
        dst[q] = s;
    }
    g_minb[row] = mn;
}

__global__ void noop_kernel() {}

// ---------------------------------------------------------------------------
// K3: fused scan+fix (unchanged, proven)
// ---------------------------------------------------------------------------
__device__ void fix_one(const float* __restrict__ x, int row0, int t, int d) {
    int s = t - 1;
    while (s >= 0) {
        float xs = x[((size_t)(row0 + s) << 10) + d];
        if (xs * g_minb[row0 + s] >= 1.0f) break;
        s--;
    }
    float h[N_ST];
    const float hinit = (s >= 0) ? 1.0f : 0.0f;
    #pragma unroll
    for (int n = 0; n < N_ST; n++) h[n] = hinit;

    const float4* ar = (const float4*)(g_sgA + (size_t)d * N_ST);
    for (int u = s + 1; u <= t; u++) {
        const float xu = x[((size_t)(row0 + u) << 10) + d];
        const float4* bp = (const float4*)(g_bproj + ((size_t)(row0 + u) << 6));
        #pragma unroll
        for (int q = 0; q < 16; q++) {
            float4 av = ar[q];
            float4 bv = bp[q];
            h[4 * q + 0] = fminf(fmaf(bv.x, xu, h[4 * q + 0] * av.x), 1.0f);
            h[4 * q + 1] = fminf(fmaf(bv.y, xu, h[4 * q + 1] * av.y), 1.0f);
            h[4 * q + 2] = fminf(fmaf(bv.z, xu, h[4 * q + 2] * av.z), 1.0f);
            h[4 * q + 3] = fminf(fmaf(bv.w, xu, h[4 * q + 3] * av.w), 1.0f);
        }
    }

    const float4* cr = (const float4*)(g_sgC + (size_t)d * N_ST);
    float y0 = 0.f, y1 = 0.f, y2 = 0.f, y3 = 0.f;
    #pragma unroll
    for (int q = 0; q < 16; q++) {
        float4 cv = cr[q];
        y0 = fmaf(h[4 * q + 0], cv.x, y0);
        y1 = fmaf(h[4 * q + 1], cv.y, y1);
        y2 = fmaf(h[4 * q + 2], cv.z, y2);
        y3 = fmaf(h[4 * q + 3], cv.w, y3);
    }
    g_yraw[((size_t)(row0 + t) << 10) + d] = (y0 + y1) + (y2 + y3);
}

__global__ __launch_bounds__(256) void scanfix_kernel(const float* __restrict__ x) {
    const int w   = blockIdx.x * 256 + threadIdx.x;
    const int row = w >> 5;
    const float mb = g_minb[row];
    const float4* xp = (const float4*)(x + ((size_t)w << 5));

    unsigned m = 0u;
    #pragma unroll
    for (int j = 0; j < 8; j++) {
        float4 v = xp[j];
        if (v.x * mb < 1.0f) m |= 1u << (4 * j + 0);
        if (v.y * mb < 1.0f) m |= 1u << (4 * j + 1);
        if (v.z * mb < 1.0f) m |= 1u << (4 * j + 2);
        if (v.w * mb < 1.0f) m |= 1u << (4 * j + 3);
    }
    if (m == 0u) return;

    const int row0  = row & ~(S_LEN - 1);
    const int t     = row & (S_LEN - 1);
    const int dbase = (w & 31) * 32;
    while (m) {
        const int c = __ffs(m) - 1;
        m &= m - 1;
        fix_one(x, row0, t, dbase + c);
    }
}

// ---------------------------------------------------------------------------
// K4: TopologicalNorm + residual + clip (unchanged, proven)
// ---------------------------------------------------------------------------
__global__ __launch_bounds__(256) void ln_kernel(const float* __restrict__ x,
                                                 float* __restrict__ out) {
    const int row  = blockIdx.x * 8 + (threadIdx.x >> 5);
    const int lane = threadIdx.x & 31;

    const float mb = g_minb[row];
    const float* yrawr = g_yraw + ((size_t)row << 10);
    const float4* xr   = (const float4*)(x + ((size_t)row << 10));
    float4*       orow = (float4*)(out + ((size_t)row << 10));
    const float4* gr   = (const float4*)g_sgG;
    const float4* sr   = (const float4*)g_sumC;

    float4 v[8], xv[8];
    float sum = 0.0f;
    #pragma unroll
    for (int i = 0; i < 8; i++) {
        const int idx = lane + 32 * i;
        float4 x4 = xr[idx];
        float4 s4 = sr[idx];
        float4 y4;
        y4.x = (x4.x * mb >= 1.0f) ? s4.x : yrawr[4 * idx + 0];
        y4.y = (x4.y * mb >= 1.0f) ? s4.y : yrawr[4 * idx + 1];
        y4.z = (x4.z * mb >= 1.0f) ? s4.z : yrawr[4 * idx + 2];
        y4.w = (x4.w * mb >= 1.0f) ? s4.w : yrawr[4 * idx + 3];
        v[i] = y4;
        xv[i] = x4;
        sum += (y4.x + y4.y) + (y4.z + y4.w);
    }
    #pragma unroll
    for (int o = 16; o > 0; o >>= 1) sum += __shfl_xor_sync(0xffffffffu, sum, o);
    const float mean = sum * (1.0f / 1024.0f);

    float ss = 0.0f;
    #pragma unroll
    for (int i = 0; i < 8; i++) {
        float dx = v[i].x - mean, dy = v[i].y - mean;
        float dz = v[i].z - mean, dw = v[i].w - mean;
        ss += (dx * dx + dy * dy) + (dz * dz + dw * dw);
    }
    #pragma unroll
    for (int o = 16; o > 0; o >>= 1) ss += __shfl_xor_sync(0xffffffffu, ss, o);
    const float rstd = rsqrtf(ss * (1.0f / 1024.0f) + 1e-5f);

    #pragma unroll
    for (int i = 0; i < 8; i++) {
        float4 g4 = gr[lane + 32 * i];
        float4 o4;
        o4.x = fminf(fmaxf((v[i].x - mean) * rstd * g4.x + xv[i].x, 0.0f), 1.0f);
        o4.y = fminf(fmaxf((v[i].y - mean) * rstd * g4.y + xv[i].y, 0.0f), 1.0f);
        o4.z = fminf(fmaxf((v[i].z - mean) * rstd * g4.z + xv[i].z, 0.0f), 1.0f);
        o4.w = fminf(fmaxf((v[i].w - mean) * rstd * g4.w + xv[i].w, 0.0f), 1.0f);
        orow[lane + 32 * i] = o4;
    }
}

// ---------------------------------------------------------------------------
// ncu captures 0-based launch index 3 -> split-K bproj_gemm this round.
// ---------------------------------------------------------------------------
extern "C" void kernel_launch(void* const* d_in, const int* in_sizes, int n_in,
                              void* d_out, int out_size) {
    const float* x     = (const float*)d_in[0];
    const float* A     = (const float*)d_in[1];
    const float* WB    = (const float*)d_in[2];
    const float* WC    = (const float*)d_in[3];
    const float* gamma = (const float*)d_in[4];
    float* out = (float*)d_out;

    noop_kernel<<<1, 32>>>();                              // 0
    noop_kernel<<<1, 32>>>();                              // 1
    precompute_kernel<<<256, 256>>>(A, WB, WC, gamma);     // 2
    bproj_gemm<<<(M_TOT / 128) * KSPLIT, 128>>>(x);        // 3  <- profiled
    reduce_kernel<<<M_TOT / 256, 256>>>();                 // 4
    scanfix_kernel<<<M_TOT * D_DIM / 32 / 256, 256>>>(x);  // 5
    ln_kernel<<<M_TOT / 8, 256>>>(x, out);                 // 6
}